// round 8
// baseline (speedup 1.0000x reference)
#include <cuda_runtime.h>

// image [1,128,128,512] f32 NHWC, RoI [N,4] f32 (cx,cy,w,h), POOL=7, STRIDE=16.
#define POOL    7
#define HH      128
#define WW      128
#define CC      512
#define NMAX    1024
#define MAXCELL (NMAX * POOL * POOL)

// Per-cell params (allocation-free rule: __device__ globals).
__device__ int4   g_off[MAXCELL];   // 4 corner offsets, float4 units
__device__ float4 g_w  [MAXCELL];   // 4 bilinear weights

// ---------------------------------------------------------------------------
// Kernel 1: one thread per (roi, py, px) cell -> corner offsets + weights.
// Matches reference math exactly (rintf = round-half-even, floor, clip order).
// ---------------------------------------------------------------------------
__global__ void roi_prep_kernel(const float* __restrict__ roi, int totalCells)
{
    int cell = blockIdx.x * blockDim.x + threadIdx.x;
    if (cell >= totalCells) return;

    int n   = cell / (POOL * POOL);
    int rem = cell - n * (POOL * POOL);
    int py  = rem / POOL;
    int px  = rem - py * POOL;

    const float inv_stride = 1.0f / 16.0f;
    float cx = roi[n * 4 + 0];
    float cy = roi[n * 4 + 1];
    float w  = roi[n * 4 + 2];
    float h  = roi[n * 4 + 3];

    float r  = rintf((cx - 0.5f * w) * inv_stride);   // x start (col)
    float c  = rintf((cy - 0.5f * h) * inv_stride);   // y start (row)
    float wq = fmaxf(rintf(w * inv_stride), 1.0f);
    float hq = fmaxf(rintf(h * inv_stride), 1.0f);

    // y axis (rows, limit HH)
    float gy  = (py + 0.5f) / (float)POOL;
    float sy  = fminf(fmaxf(gy * hq - 0.5f, 0.0f), hq - 1.0f);
    float fy0 = floorf(sy);
    float ly  = sy - fy0;
    float fy1 = fminf(fy0 + 1.0f, hq - 1.0f);
    int iy0 = (int)fminf(fmaxf(c + fy0, 0.0f), (float)(HH - 1));
    int iy1 = (int)fminf(fmaxf(c + fy1, 0.0f), (float)(HH - 1));

    // x axis (cols, limit WW)
    float gx  = (px + 0.5f) / (float)POOL;
    float sx  = fminf(fmaxf(gx * wq - 0.5f, 0.0f), wq - 1.0f);
    float fx0 = floorf(sx);
    float lx  = sx - fx0;
    float fx1 = fminf(fx0 + 1.0f, wq - 1.0f);
    int ix0 = (int)fminf(fmaxf(r + fx0, 0.0f), (float)(WW - 1));
    int ix1 = (int)fminf(fmaxf(r + fx1, 0.0f), (float)(WW - 1));

    g_off[cell] = make_int4((iy0 * WW + ix0) * (CC / 4),
                            (iy0 * WW + ix1) * (CC / 4),
                            (iy1 * WW + ix0) * (CC / 4),
                            (iy1 * WW + ix1) * (CC / 4));
    g_w[cell] = make_float4((1.0f - ly) * (1.0f - lx),
                            (1.0f - ly) * lx,
                            ly * (1.0f - lx),
                            ly * lx);
}

// ---------------------------------------------------------------------------
// Kernel 2: 64 threads per cell, each thread owns 2 float4 lanes x 4 corners
// = 8 independent LDG.128. __launch_bounds__(256, 4) raises the register cap
// to 64 so ptxas can keep ALL 8 loads in flight (32 payload regs + addresses)
// instead of splitting into load-4/consume-4 waves (regs=38 last round).
// ---------------------------------------------------------------------------
__global__ __launch_bounds__(256, 4)
void roi_pool_kernel(const float* __restrict__ img, float* __restrict__ out,
                     int totalCells)
{
    int tid  = threadIdx.x;
    int cell = blockIdx.x * 4 + (tid >> 6);
    if (cell >= totalCells) return;
    int t4   = tid & 63;               // first lane; second is t4+64

    // Param loads first (same 32B line, broadcast across 64 threads).
    int4   o = g_off[cell];
    float4 w = g_w[cell];

    const float4* __restrict__ img4 = (const float4*)img;
    const float4* pa = img4 + o.x + t4;
    const float4* pb = img4 + o.y + t4;
    const float4* pc = img4 + o.z + t4;
    const float4* pd = img4 + o.w + t4;

    // 8 independent loads (4 corners x 2 lanes) — front-batched.
    float4 a0 = __ldg(pa);
    float4 b0 = __ldg(pb);
    float4 c0 = __ldg(pc);
    float4 d0 = __ldg(pd);
    float4 a1 = __ldg(pa + 64);
    float4 b1 = __ldg(pb + 64);
    float4 c1 = __ldg(pc + 64);
    float4 d1 = __ldg(pd + 64);

    float4 r0, r1;
    r0.x = w.x * a0.x + w.y * b0.x + w.z * c0.x + w.w * d0.x;
    r0.y = w.x * a0.y + w.y * b0.y + w.z * c0.y + w.w * d0.y;
    r0.z = w.x * a0.z + w.y * b0.z + w.z * c0.z + w.w * d0.z;
    r0.w = w.x * a0.w + w.y * b0.w + w.z * c0.w + w.w * d0.w;
    r1.x = w.x * a1.x + w.y * b1.x + w.z * c1.x + w.w * d1.x;
    r1.y = w.x * a1.y + w.y * b1.y + w.z * c1.y + w.w * d1.y;
    r1.z = w.x * a1.z + w.y * b1.z + w.z * c1.z + w.w * d1.z;
    r1.w = w.x * a1.w + w.y * b1.w + w.z * c1.w + w.w * d1.w;

    float4* __restrict__ out4 = (float4*)out + (size_t)cell * (CC / 4);
    __stcs(out4 + t4,      r0);
    __stcs(out4 + t4 + 64, r1);
}

extern "C" void kernel_launch(void* const* d_in, const int* in_sizes, int n_in,
                              void* d_out, int out_size)
{
    const float* img = (const float*)d_in[0];   // [1,128,128,512] f32
    const float* roi = (const float*)d_in[1];   // [N,4] f32
    float*       out = (float*)d_out;           // [1,N,7,7,512] f32

    int N = in_sizes[1] / 4;
    if (N > NMAX) N = NMAX;
    int totalCells = N * POOL * POOL;

    roi_prep_kernel<<<(totalCells + 255) / 256, 256>>>(roi, totalCells);
    roi_pool_kernel<<<(totalCells + 3) / 4, 256>>>(img, out, totalCells);
}